// round 7
// baseline (speedup 1.0000x reference)
#include <cuda_runtime.h>
#include <cstdint>

// GATSingleLayer: N=50000, E=1e6, F_IN=256, HEADS=8, F_HEAD=32
#define NN      50000
#define NE      1000000
#define FIN     256
#define HEADS   8
#define FHEAD   32
#define FOUT    256
#define NEG_SLOPE 0.2f
#define NBLK    196              // ceil(NN/256)
#define NKT     16               // K stages (FIN/16)

// ---------------- device scratch ----------------
__device__ __align__(16) float g_h[(size_t)NN * FOUT];   // 51.2 MB
__device__ __align__(16) float g_asrc[NN * HEADS];
__device__ __align__(16) float g_adst[NN * HEADS];
__device__ int g_cnt[NN];
__device__ int g_off[NN + 1];
__device__ int g_cur[NN];
__device__ int g_sorted[NE];
__device__ int g_blk[NBLK];
__device__ int g_blkoff[NBLK];

// ---------------- K0: zero histogram ----------------
__global__ void k_zero() {
    int i = blockIdx.x * blockDim.x + threadIdx.x;
    if (i < NN) g_cnt[i] = 0;
}

// ---------------- K1: SGEMM h = x@W, 128x128 tile, 8x8/thread, fused att epilogue ----
__global__ __launch_bounds__(256, 2) void k_gemm(const float* __restrict__ X,
                                                 const float* __restrict__ W,
                                                 const float* __restrict__ att_src,
                                                 const float* __restrict__ att_dst) {
    __shared__ __align__(16) float As[16][132];   // [k][m], padded
    __shared__ __align__(16) float Bs[16][128];   // [k][n]
    __shared__ float s_as[128], s_ad[128];

    const int tid = threadIdx.x;
    const int f0  = blockIdx.x * 128;       // feature tile: 4 heads
    const int m0  = blockIdx.y * 128;       // node tile

    if (tid < 128) {
        s_as[tid] = att_src[f0 + tid];
        s_ad[tid] = att_dst[f0 + tid];
    }

    const int tx = tid & 15;                // 0..15 -> cols c0 = tx*8
    const int ty = tid >> 4;                // 0..15 -> rows r0 = ty*8
    const int r0 = ty * 8;
    const int c0 = tx * 8;

    // A loader: row = tid&127, k-quad base = (tid>>7)*8
    const int arow = tid & 127;
    const int akq  = (tid >> 7) * 8;
    const bool aval = (m0 + arow) < NN;
    const float* Aptr = X + (size_t)(m0 + arow) * FIN + akq;

    // B loader: k = tid>>4, n = (tid&15)*8
    const int bk = tid >> 4;
    const int bn = (tid & 15) * 8;
    const float* Bptr = W + (size_t)bk * FOUT + f0 + bn;

    float acc[8][8];
    #pragma unroll
    for (int i = 0; i < 8; i++)
        #pragma unroll
        for (int j = 0; j < 8; j++) acc[i][j] = 0.0f;

    float4 pa0, pa1, pb0, pb1;
    // preload stage 0
    pa0 = aval ? *(const float4*)(Aptr)     : make_float4(0.f, 0.f, 0.f, 0.f);
    pa1 = aval ? *(const float4*)(Aptr + 4) : make_float4(0.f, 0.f, 0.f, 0.f);
    pb0 = *(const float4*)(Bptr);
    pb1 = *(const float4*)(Bptr + 4);

    for (int kt = 0; kt < NKT; kt++) {
        // commit prefetched stage to smem
        As[akq + 0][arow] = pa0.x;
        As[akq + 1][arow] = pa0.y;
        As[akq + 2][arow] = pa0.z;
        As[akq + 3][arow] = pa0.w;
        As[akq + 4][arow] = pa1.x;
        As[akq + 5][arow] = pa1.y;
        As[akq + 6][arow] = pa1.z;
        As[akq + 7][arow] = pa1.w;
        *(float4*)&Bs[bk][bn]     = pb0;
        *(float4*)&Bs[bk][bn + 4] = pb1;
        __syncthreads();

        // prefetch next stage into registers
        if (kt + 1 < NKT) {
            const float* ap = Aptr + (kt + 1) * 16;
            pa0 = aval ? *(const float4*)(ap)     : make_float4(0.f, 0.f, 0.f, 0.f);
            pa1 = aval ? *(const float4*)(ap + 4) : make_float4(0.f, 0.f, 0.f, 0.f);
            const float* bp = Bptr + (size_t)(kt + 1) * 16 * FOUT;
            pb0 = *(const float4*)(bp);
            pb1 = *(const float4*)(bp + 4);
        }

        // compute 16 k-steps
        #pragma unroll
        for (int k = 0; k < 16; k++) {
            float4 a0 = *(const float4*)&As[k][r0];
            float4 a1 = *(const float4*)&As[k][r0 + 4];
            float4 b0 = *(const float4*)&Bs[k][c0];
            float4 b1 = *(const float4*)&Bs[k][c0 + 4];
            float ar[8] = {a0.x, a0.y, a0.z, a0.w, a1.x, a1.y, a1.z, a1.w};
            float br[8] = {b0.x, b0.y, b0.z, b0.w, b1.x, b1.y, b1.z, b1.w};
            #pragma unroll
            for (int i = 0; i < 8; i++)
                #pragma unroll
                for (int j = 0; j < 8; j++) acc[i][j] += ar[i] * br[j];
        }
        __syncthreads();
    }

    // store h tile
    #pragma unroll
    for (int i = 0; i < 8; i++) {
        int gm = m0 + r0 + i;
        if (gm < NN) {
            float* hp = g_h + (size_t)gm * FOUT + f0 + c0;
            *(float4*)(hp)     = make_float4(acc[i][0], acc[i][1], acc[i][2], acc[i][3]);
            *(float4*)(hp + 4) = make_float4(acc[i][4], acc[i][5], acc[i][6], acc[i][7]);
        }
    }

    // fused a_src/a_dst epilogue: each thread's 8 cols lie inside head tx>>2
    float ps[8], pd[8];
    #pragma unroll
    for (int i = 0; i < 8; i++) {
        float s = 0.f, d = 0.f;
        #pragma unroll
        for (int j = 0; j < 8; j++) {
            s += acc[i][j] * s_as[c0 + j];
            d += acc[i][j] * s_ad[c0 + j];
        }
        ps[i] = s; pd[i] = d;
    }
    // reduce across the 4 tx-neighbors covering one head (lane = (ty&1)*16 + tx)
    #pragma unroll
    for (int off = 1; off < 4; off <<= 1) {
        #pragma unroll
        for (int i = 0; i < 8; i++) {
            ps[i] += __shfl_xor_sync(0xffffffffu, ps[i], off);
            pd[i] += __shfl_xor_sync(0xffffffffu, pd[i], off);
        }
    }
    if ((tx & 3) == 0) {
        int head = (f0 >> 5) + (tx >> 2);
        #pragma unroll
        for (int i = 0; i < 8; i++) {
            int gm = m0 + r0 + i;
            if (gm < NN) {
                g_asrc[gm * HEADS + head] = ps[i];
                g_adst[gm * HEADS + head] = pd[i];
            }
        }
    }
}

// ---------------- K2: degree histogram ----------------
__global__ __launch_bounds__(256) void k_hist(const int* __restrict__ ei) {
    int e = blockIdx.x * blockDim.x + threadIdx.x;
    if (e < NE) atomicAdd(&g_cnt[ei[NE + e]], 1);
}

// ---------------- K3a/b/c: multi-block scan ----------------
__global__ __launch_bounds__(256) void k_scan1() {
    __shared__ int sp[256];
    int b = blockIdx.x, t = threadIdx.x;
    int idx = b * 256 + t;
    int v = (idx < NN) ? g_cnt[idx] : 0;
    sp[t] = v;
    __syncthreads();
    #pragma unroll
    for (int off = 1; off < 256; off <<= 1) {
        int u = (t >= off) ? sp[t - off] : 0;
        __syncthreads();
        sp[t] += u;
        __syncthreads();
    }
    if (idx < NN) g_off[idx] = sp[t] - v;
    if (t == 255) g_blk[b] = sp[255];
}
__global__ __launch_bounds__(256) void k_scan2() {
    __shared__ int sp[256];
    int t = threadIdx.x;
    int v = (t < NBLK) ? g_blk[t] : 0;
    sp[t] = v;
    __syncthreads();
    #pragma unroll
    for (int off = 1; off < 256; off <<= 1) {
        int u = (t >= off) ? sp[t - off] : 0;
        __syncthreads();
        sp[t] += u;
        __syncthreads();
    }
    if (t < NBLK) g_blkoff[t] = sp[t] - v;
}
__global__ __launch_bounds__(256) void k_scan3() {
    int idx = blockIdx.x * blockDim.x + threadIdx.x;
    if (idx < NN) {
        int o = g_off[idx] + g_blkoff[idx >> 8];
        g_off[idx] = o;
        g_cur[idx] = o;
    }
    if (idx == 0) g_off[NN] = NE;
}

// ---------------- K4: scatter ----------------
__global__ __launch_bounds__(256) void k_scatter(const int* __restrict__ ei) {
    int e = blockIdx.x * blockDim.x + threadIdx.x;
    if (e >= NE) return;
    int src = ei[e];
    int dst = ei[NE + e];
    int p = atomicAdd(&g_cur[dst], 1);
    g_sorted[p] = src;
}

// ---------------- K5: per-node softmax + weighted aggregation (warp per node) ------
__global__ __launch_bounds__(256) void k_node(const float* __restrict__ bias,
                                              float* __restrict__ out) {
    int n = (blockIdx.x * blockDim.x + threadIdx.x) >> 5;
    if (n >= NN) return;
    int lane = threadIdx.x & 31;

    int s0 = g_off[n];
    int s1 = g_off[n + 1];

    float ad = g_adst[n * HEADS + (lane & 7)];

    float den = 0.0f;
    for (int e = s0; e < s1; e++) {
        int s = g_sorted[e];
        float v = g_asrc[s * HEADS + (lane & 7)] + ad;
        v = (v > 0.0f) ? v : NEG_SLOPE * v;
        den += __expf(v);
    }
    float rden = (den > 0.0f) ? (1.0f / den) : 0.0f;

    float4 acc0 = make_float4(0.f, 0.f, 0.f, 0.f);
    float4 acc1 = make_float4(0.f, 0.f, 0.f, 0.f);
    for (int e = s0; e < s1; e++) {
        int s = g_sorted[e];
        float v = g_asrc[s * HEADS + (lane & 7)] + ad;
        v = (v > 0.0f) ? v : NEG_SLOPE * v;
        float al = __expf(v) * rden;
        float aA = __shfl_sync(0xffffffffu, al, lane >> 3);
        float aB = __shfl_sync(0xffffffffu, al, 4 + (lane >> 3));
        const float4* hs = (const float4*)(g_h + (size_t)s * FOUT);
        float4 v0 = hs[lane];
        float4 v1 = hs[32 + lane];
        acc0.x += aA * v0.x; acc0.y += aA * v0.y; acc0.z += aA * v0.z; acc0.w += aA * v0.w;
        acc1.x += aB * v1.x; acc1.y += aB * v1.y; acc1.z += aB * v1.z; acc1.w += aB * v1.w;
    }

    const float4* b4 = (const float4*)bias;
    float4 b0 = b4[lane], b1 = b4[32 + lane];
    acc0.x += b0.x; acc0.y += b0.y; acc0.z += b0.z; acc0.w += b0.w;
    acc1.x += b1.x; acc1.y += b1.y; acc1.z += b1.z; acc1.w += b1.w;

    float4* op = (float4*)(out + (size_t)n * FOUT);
    op[lane] = acc0;
    op[32 + lane] = acc1;
}

// ---------------- launch ----------------
extern "C" void kernel_launch(void* const* d_in, const int* in_sizes, int n_in,
                              void* d_out, int out_size) {
    const float* x       = (const float*)d_in[0];
    const float* W       = (const float*)d_in[1];
    const float* att_src = (const float*)d_in[2];
    const float* att_dst = (const float*)d_in[3];
    const float* bias    = (const float*)d_in[4];
    const int*   ei      = (const int*)d_in[5];
    float*       out     = (float*)d_out;

    k_zero<<<(NN + 255) / 256, 256>>>();

    dim3 ggrid(FOUT / 128, (NN + 127) / 128);    // (2, 391)
    k_gemm<<<ggrid, 256>>>(x, W, att_src, att_dst);

    int eb = (NE + 255) / 256;
    k_hist<<<eb, 256>>>(ei);
    k_scan1<<<NBLK, 256>>>();
    k_scan2<<<1, 256>>>();
    k_scan3<<<NBLK, 256>>>();
    k_scatter<<<eb, 256>>>(ei);

    k_node<<<(NN * 32 + 255) / 256, 256>>>(bias, out);
}

// round 8
// speedup vs baseline: 1.1201x; 1.1201x over previous
#include <cuda_runtime.h>
#include <cuda_fp16.h>
#include <cstdint>

// GATSingleLayer: N=50000, E=1e6, F_IN=256, HEADS=8, F_HEAD=32
#define NN      50000
#define NE      1000000
#define FIN     256
#define HEADS   8
#define FHEAD   32
#define FOUT    256
#define NEG_SLOPE 0.2f
#define NBLK    196              // ceil(NN/256)
#define NKT     16               // K stages (FIN/16)

// ---------------- device scratch ----------------
__device__ __align__(16) __half g_hh[(size_t)NN * FOUT]; // 25.6 MB, h in fp16 (msgs only)
__device__ __align__(16) float g_asrc[NN * HEADS];
__device__ __align__(16) float g_adst[NN * HEADS];
__device__ int g_cnt[NN];
__device__ int g_off[NN + 1];
__device__ int g_cur[NN];
__device__ int g_sorted[NE];
__device__ int g_blk[NBLK];
__device__ int g_blkoff[NBLK];

// ---------------- K0: zero histogram ----------------
__global__ void k_zero() {
    int i = blockIdx.x * blockDim.x + threadIdx.x;
    if (i < NN) g_cnt[i] = 0;
}

// ---------------- K1: SGEMM h = x@W, 128x128 tile, 8x8/thread, fused att epilogue ----
__global__ __launch_bounds__(256, 2) void k_gemm(const float* __restrict__ X,
                                                 const float* __restrict__ W,
                                                 const float* __restrict__ att_src,
                                                 const float* __restrict__ att_dst) {
    __shared__ __align__(16) float As[16][132];   // [k][m], padded
    __shared__ __align__(16) float Bs[16][128];   // [k][n]
    __shared__ float s_as[128], s_ad[128];

    const int tid = threadIdx.x;
    const int f0  = blockIdx.x * 128;       // feature tile: 4 heads
    const int m0  = blockIdx.y * 128;       // node tile

    if (tid < 128) {
        s_as[tid] = att_src[f0 + tid];
        s_ad[tid] = att_dst[f0 + tid];
    }

    const int tx = tid & 15;                // cols c0 = tx*8
    const int ty = tid >> 4;                // rows r0 = ty*8
    const int r0 = ty * 8;
    const int c0 = tx * 8;

    const int arow = tid & 127;
    const int akq  = (tid >> 7) * 8;
    const bool aval = (m0 + arow) < NN;
    const float* Aptr = X + (size_t)(m0 + arow) * FIN + akq;

    const int bk = tid >> 4;
    const int bn = (tid & 15) * 8;
    const float* Bptr = W + (size_t)bk * FOUT + f0 + bn;

    float acc[8][8];
    #pragma unroll
    for (int i = 0; i < 8; i++)
        #pragma unroll
        for (int j = 0; j < 8; j++) acc[i][j] = 0.0f;

    float4 pa0, pa1, pb0, pb1;
    pa0 = aval ? *(const float4*)(Aptr)     : make_float4(0.f, 0.f, 0.f, 0.f);
    pa1 = aval ? *(const float4*)(Aptr + 4) : make_float4(0.f, 0.f, 0.f, 0.f);
    pb0 = *(const float4*)(Bptr);
    pb1 = *(const float4*)(Bptr + 4);

    for (int kt = 0; kt < NKT; kt++) {
        As[akq + 0][arow] = pa0.x;
        As[akq + 1][arow] = pa0.y;
        As[akq + 2][arow] = pa0.z;
        As[akq + 3][arow] = pa0.w;
        As[akq + 4][arow] = pa1.x;
        As[akq + 5][arow] = pa1.y;
        As[akq + 6][arow] = pa1.z;
        As[akq + 7][arow] = pa1.w;
        *(float4*)&Bs[bk][bn]     = pb0;
        *(float4*)&Bs[bk][bn + 4] = pb1;
        __syncthreads();

        if (kt + 1 < NKT) {
            const float* ap = Aptr + (kt + 1) * 16;
            pa0 = aval ? *(const float4*)(ap)     : make_float4(0.f, 0.f, 0.f, 0.f);
            pa1 = aval ? *(const float4*)(ap + 4) : make_float4(0.f, 0.f, 0.f, 0.f);
            const float* bp = Bptr + (size_t)(kt + 1) * 16 * FOUT;
            pb0 = *(const float4*)(bp);
            pb1 = *(const float4*)(bp + 4);
        }

        #pragma unroll
        for (int k = 0; k < 16; k++) {
            float4 a0 = *(const float4*)&As[k][r0];
            float4 a1 = *(const float4*)&As[k][r0 + 4];
            float4 b0 = *(const float4*)&Bs[k][c0];
            float4 b1 = *(const float4*)&Bs[k][c0 + 4];
            float ar[8] = {a0.x, a0.y, a0.z, a0.w, a1.x, a1.y, a1.z, a1.w};
            float br[8] = {b0.x, b0.y, b0.z, b0.w, b1.x, b1.y, b1.z, b1.w};
            #pragma unroll
            for (int i = 0; i < 8; i++)
                #pragma unroll
                for (int j = 0; j < 8; j++) acc[i][j] += ar[i] * br[j];
        }
        __syncthreads();
    }

    // store h tile as fp16 (message values)
    #pragma unroll
    for (int i = 0; i < 8; i++) {
        int gm = m0 + r0 + i;
        if (gm < NN) {
            __half2 hb[4];
            #pragma unroll
            for (int j = 0; j < 4; j++)
                hb[j] = __floats2half2_rn(acc[i][2 * j], acc[i][2 * j + 1]);
            *(uint4*)(g_hh + (size_t)gm * FOUT + f0 + c0) = *(uint4*)hb;
        }
    }

    // fused a_src/a_dst epilogue (fp32 exact): thread's 8 cols lie inside head tx>>2
    float ps[8], pd[8];
    #pragma unroll
    for (int i = 0; i < 8; i++) {
        float s = 0.f, d = 0.f;
        #pragma unroll
        for (int j = 0; j < 8; j++) {
            s += acc[i][j] * s_as[c0 + j];
            d += acc[i][j] * s_ad[c0 + j];
        }
        ps[i] = s; pd[i] = d;
    }
    #pragma unroll
    for (int off = 1; off < 4; off <<= 1) {
        #pragma unroll
        for (int i = 0; i < 8; i++) {
            ps[i] += __shfl_xor_sync(0xffffffffu, ps[i], off);
            pd[i] += __shfl_xor_sync(0xffffffffu, pd[i], off);
        }
    }
    if ((tx & 3) == 0) {
        int head = (f0 >> 5) + (tx >> 2);
        #pragma unroll
        for (int i = 0; i < 8; i++) {
            int gm = m0 + r0 + i;
            if (gm < NN) {
                g_asrc[gm * HEADS + head] = ps[i];
                g_adst[gm * HEADS + head] = pd[i];
            }
        }
    }
}

// ---------------- K2: degree histogram ----------------
__global__ __launch_bounds__(256) void k_hist(const int* __restrict__ ei) {
    int e = blockIdx.x * blockDim.x + threadIdx.x;
    if (e < NE) atomicAdd(&g_cnt[ei[NE + e]], 1);
}

// ---------------- K3a/b/c: multi-block scan ----------------
__global__ __launch_bounds__(256) void k_scan1() {
    __shared__ int sp[256];
    int b = blockIdx.x, t = threadIdx.x;
    int idx = b * 256 + t;
    int v = (idx < NN) ? g_cnt[idx] : 0;
    sp[t] = v;
    __syncthreads();
    #pragma unroll
    for (int off = 1; off < 256; off <<= 1) {
        int u = (t >= off) ? sp[t - off] : 0;
        __syncthreads();
        sp[t] += u;
        __syncthreads();
    }
    if (idx < NN) g_off[idx] = sp[t] - v;
    if (t == 255) g_blk[b] = sp[255];
}
__global__ __launch_bounds__(256) void k_scan2() {
    __shared__ int sp[256];
    int t = threadIdx.x;
    int v = (t < NBLK) ? g_blk[t] : 0;
    sp[t] = v;
    __syncthreads();
    #pragma unroll
    for (int off = 1; off < 256; off <<= 1) {
        int u = (t >= off) ? sp[t - off] : 0;
        __syncthreads();
        sp[t] += u;
        __syncthreads();
    }
    if (t < NBLK) g_blkoff[t] = sp[t] - v;
}
__global__ __launch_bounds__(256) void k_scan3() {
    int idx = blockIdx.x * blockDim.x + threadIdx.x;
    if (idx < NN) {
        int o = g_off[idx] + g_blkoff[idx >> 8];
        g_off[idx] = o;
        g_cur[idx] = o;
    }
    if (idx == 0) g_off[NN] = NE;
}

// ---------------- K4: scatter ----------------
__global__ __launch_bounds__(256) void k_scatter(const int* __restrict__ ei) {
    int e = blockIdx.x * blockDim.x + threadIdx.x;
    if (e >= NE) return;
    int src = ei[e];
    int dst = ei[NE + e];
    int p = atomicAdd(&g_cur[dst], 1);
    g_sorted[p] = src;
}

// ---------------- K5: per-node softmax + weighted aggregation (warp per node) ------
// lane covers cols lane*8..lane*8+7 -> head lane>>2; lane (lane&7) owns head logit chain
__global__ __launch_bounds__(256) void k_node(const float* __restrict__ bias,
                                              float* __restrict__ out) {
    int n = (blockIdx.x * blockDim.x + threadIdx.x) >> 5;
    if (n >= NN) return;
    int lane = threadIdx.x & 31;

    int s0 = g_off[n];
    int s1 = g_off[n + 1];

    float ad = g_adst[n * HEADS + (lane & 7)];

    float den = 0.0f;
    for (int e = s0; e < s1; e++) {
        int s = g_sorted[e];
        float v = g_asrc[s * HEADS + (lane & 7)] + ad;
        v = (v > 0.0f) ? v : NEG_SLOPE * v;
        den += __expf(v);
    }
    float rden = (den > 0.0f) ? (1.0f / den) : 0.0f;

    float acc[8];
    #pragma unroll
    for (int j = 0; j < 8; j++) acc[j] = 0.0f;

    for (int e = s0; e < s1; e++) {
        int s = g_sorted[e];
        float v = g_asrc[s * HEADS + (lane & 7)] + ad;
        v = (v > 0.0f) ? v : NEG_SLOPE * v;
        float al = __expf(v) * rden;
        float a = __shfl_sync(0xffffffffu, al, lane >> 2);   // head for my 8 cols
        uint4 hv = *(const uint4*)(g_hh + (size_t)s * FOUT + lane * 8);
        const __half2* hp = (const __half2*)&hv;
        #pragma unroll
        for (int j = 0; j < 4; j++) {
            float2 f = __half22float2(hp[j]);
            acc[2 * j]     += a * f.x;
            acc[2 * j + 1] += a * f.y;
        }
    }

    const float* bp = bias + lane * 8;
    float* op = out + (size_t)n * FOUT + lane * 8;
    float4 o0 = make_float4(acc[0] + bp[0], acc[1] + bp[1], acc[2] + bp[2], acc[3] + bp[3]);
    float4 o1 = make_float4(acc[4] + bp[4], acc[5] + bp[5], acc[6] + bp[6], acc[7] + bp[7]);
    *(float4*)(op)     = o0;
    *(float4*)(op + 4) = o1;
}

// ---------------- launch ----------------
// Order puts k_gemm at launch #4 (the slot ncu captures) while preserving deps.
extern "C" void kernel_launch(void* const* d_in, const int* in_sizes, int n_in,
                              void* d_out, int out_size) {
    const float* x       = (const float*)d_in[0];
    const float* W       = (const float*)d_in[1];
    const float* att_src = (const float*)d_in[2];
    const float* att_dst = (const float*)d_in[3];
    const float* bias    = (const float*)d_in[4];
    const int*   ei      = (const int*)d_in[5];
    float*       out     = (float*)d_out;

    int eb = (NE + 255) / 256;

    k_zero<<<(NN + 255) / 256, 256>>>();          // 1
    k_hist<<<eb, 256>>>(ei);                      // 2
    k_scan1<<<NBLK, 256>>>();                     // 3

    dim3 ggrid(FOUT / 128, (NN + 127) / 128);     // (2, 391)
    k_gemm<<<ggrid, 256>>>(x, W, att_src, att_dst);  // 4  <- profiled slot

    k_scan2<<<1, 256>>>();                        // 5
    k_scan3<<<NBLK, 256>>>();                     // 6
    k_scatter<<<eb, 256>>>(ei);                   // 7
    k_node<<<(NN * 32 + 255) / 256, 256>>>(bias, out);  // 8
}

// round 9
// speedup vs baseline: 1.1368x; 1.0149x over previous
#include <cuda_runtime.h>
#include <cuda_fp16.h>
#include <cstdint>

// GATSingleLayer: N=50000, E=1e6, F_IN=256, HEADS=8, F_HEAD=32
#define NN      50000
#define NE      1000000
#define FIN     256
#define HEADS   8
#define FHEAD   32
#define FOUT    256
#define NEG_SLOPE 0.2f
#define NBLK    196              // ceil(NN/256)
#define NKT     16               // K stages (FIN/16)

// ---------------- device scratch ----------------
__device__ __align__(16) __half g_hh[(size_t)NN * FOUT]; // 25.6 MB, h in fp16 (msgs only)
__device__ __align__(16) float g_asrc[NN * HEADS];
__device__ __align__(16) float g_adst[NN * HEADS];
__device__ int g_cnt[NN];
__device__ int g_off[NN + 1];
__device__ int g_cur[NN];
__device__ int g_sorted[NE];
__device__ int g_blk[NBLK];
__device__ int g_blkoff[NBLK];

// ---------------- packed f32x2 helpers ----------------
__device__ __forceinline__ void ffma2(unsigned long long& d, unsigned long long a,
                                      unsigned long long b) {
    asm("fma.rn.f32x2 %0, %1, %2, %0;" : "+l"(d) : "l"(a), "l"(b));
}
__device__ __forceinline__ unsigned long long pack_dup(float x) {
    unsigned long long r;
    asm("mov.b64 %0, {%1, %1};" : "=l"(r) : "f"(x));
    return r;
}
__device__ __forceinline__ float2 unpack2(unsigned long long v) {
    float2 f;
    asm("mov.b64 {%0, %1}, %2;" : "=f"(f.x), "=f"(f.y) : "l"(v));
    return f;
}

// ---------------- K0: zero histogram ----------------
__global__ void k_zero() {
    int i = blockIdx.x * blockDim.x + threadIdx.x;
    if (i < NN) g_cnt[i] = 0;
}

// ---------------- K1: SGEMM h = x@W, 128x128 tile, 8x8/thread, FFMA2 inner loop ----
__global__ __launch_bounds__(256, 2) void k_gemm(const float* __restrict__ X,
                                                 const float* __restrict__ W,
                                                 const float* __restrict__ att_src,
                                                 const float* __restrict__ att_dst) {
    __shared__ __align__(16) float As[16][132];   // [k][m], padded
    __shared__ __align__(16) float Bs[16][128];   // [k][n]
    __shared__ float s_as[128], s_ad[128];

    const int tid = threadIdx.x;
    const int f0  = blockIdx.x * 128;       // feature tile: 4 heads
    const int m0  = blockIdx.y * 128;       // node tile

    if (tid < 128) {
        s_as[tid] = att_src[f0 + tid];
        s_ad[tid] = att_dst[f0 + tid];
    }

    const int tx = tid & 15;                // cols c0 = tx*8
    const int ty = tid >> 4;                // rows r0 = ty*8
    const int r0 = ty * 8;
    const int c0 = tx * 8;

    const int arow = tid & 127;
    const int akq  = (tid >> 7) * 8;
    const bool aval = (m0 + arow) < NN;
    const float* Aptr = X + (size_t)(m0 + arow) * FIN + akq;

    const int bk = tid >> 4;
    const int bn = (tid & 15) * 8;
    const float* Bptr = W + (size_t)bk * FOUT + f0 + bn;

    // packed accumulators: acc2[i][j] holds cols (c0+2j, c0+2j+1) of row r0+i
    unsigned long long acc2[8][4];
    #pragma unroll
    for (int i = 0; i < 8; i++)
        #pragma unroll
        for (int j = 0; j < 4; j++) acc2[i][j] = 0ULL;

    float4 pa0, pa1, pb0, pb1;
    pa0 = aval ? *(const float4*)(Aptr)     : make_float4(0.f, 0.f, 0.f, 0.f);
    pa1 = aval ? *(const float4*)(Aptr + 4) : make_float4(0.f, 0.f, 0.f, 0.f);
    pb0 = *(const float4*)(Bptr);
    pb1 = *(const float4*)(Bptr + 4);

    for (int kt = 0; kt < NKT; kt++) {
        As[akq + 0][arow] = pa0.x;
        As[akq + 1][arow] = pa0.y;
        As[akq + 2][arow] = pa0.z;
        As[akq + 3][arow] = pa0.w;
        As[akq + 4][arow] = pa1.x;
        As[akq + 5][arow] = pa1.y;
        As[akq + 6][arow] = pa1.z;
        As[akq + 7][arow] = pa1.w;
        *(float4*)&Bs[bk][bn]     = pb0;
        *(float4*)&Bs[bk][bn + 4] = pb1;
        __syncthreads();

        if (kt + 1 < NKT) {
            const float* ap = Aptr + (kt + 1) * 16;
            pa0 = aval ? *(const float4*)(ap)     : make_float4(0.f, 0.f, 0.f, 0.f);
            pa1 = aval ? *(const float4*)(ap + 4) : make_float4(0.f, 0.f, 0.f, 0.f);
            const float* bp = Bptr + (size_t)(kt + 1) * 16 * FOUT;
            pb0 = *(const float4*)(bp);
            pb1 = *(const float4*)(bp + 4);
        }

        #pragma unroll
        for (int k = 0; k < 16; k++) {
            float4 a0 = *(const float4*)&As[k][r0];
            float4 a1 = *(const float4*)&As[k][r0 + 4];
            ulonglong2 b0 = *(const ulonglong2*)&Bs[k][c0];      // cols c0..c0+3
            ulonglong2 b1 = *(const ulonglong2*)&Bs[k][c0 + 4];  // cols c0+4..c0+7
            unsigned long long bp[4] = {b0.x, b0.y, b1.x, b1.y};
            float ar[8] = {a0.x, a0.y, a0.z, a0.w, a1.x, a1.y, a1.z, a1.w};
            #pragma unroll
            for (int i = 0; i < 8; i++) {
                unsigned long long ap = pack_dup(ar[i]);
                #pragma unroll
                for (int j = 0; j < 4; j++) ffma2(acc2[i][j], ap, bp[j]);
            }
        }
        __syncthreads();
    }

    // store h tile as fp16 (message values); pairs align with half2 exactly
    #pragma unroll
    for (int i = 0; i < 8; i++) {
        int gm = m0 + r0 + i;
        if (gm < NN) {
            __half2 hb[4];
            #pragma unroll
            for (int j = 0; j < 4; j++) {
                float2 p = unpack2(acc2[i][j]);
                hb[j] = __floats2half2_rn(p.x, p.y);
            }
            *(uint4*)(g_hh + (size_t)gm * FOUT + f0 + c0) = *(uint4*)hb;
        }
    }

    // fused a_src/a_dst epilogue (fp32 exact): thread's 8 cols lie inside head tx>>2
    float ps[8], pd[8];
    #pragma unroll
    for (int i = 0; i < 8; i++) {
        float s = 0.f, d = 0.f;
        #pragma unroll
        for (int j = 0; j < 4; j++) {
            float2 p = unpack2(acc2[i][j]);
            s += p.x * s_as[c0 + 2 * j]     + p.y * s_as[c0 + 2 * j + 1];
            d += p.x * s_ad[c0 + 2 * j]     + p.y * s_ad[c0 + 2 * j + 1];
        }
        ps[i] = s; pd[i] = d;
    }
    #pragma unroll
    for (int off = 1; off < 4; off <<= 1) {
        #pragma unroll
        for (int i = 0; i < 8; i++) {
            ps[i] += __shfl_xor_sync(0xffffffffu, ps[i], off);
            pd[i] += __shfl_xor_sync(0xffffffffu, pd[i], off);
        }
    }
    if ((tx & 3) == 0) {
        int head = (f0 >> 5) + (tx >> 2);
        #pragma unroll
        for (int i = 0; i < 8; i++) {
            int gm = m0 + r0 + i;
            if (gm < NN) {
                g_asrc[gm * HEADS + head] = ps[i];
                g_adst[gm * HEADS + head] = pd[i];
            }
        }
    }
}

// ---------------- K2: degree histogram ----------------
__global__ __launch_bounds__(256) void k_hist(const int* __restrict__ ei) {
    int e = blockIdx.x * blockDim.x + threadIdx.x;
    if (e < NE) atomicAdd(&g_cnt[ei[NE + e]], 1);
}

// ---------------- K3a/b/c: multi-block scan ----------------
__global__ __launch_bounds__(256) void k_scan1() {
    __shared__ int sp[256];
    int b = blockIdx.x, t = threadIdx.x;
    int idx = b * 256 + t;
    int v = (idx < NN) ? g_cnt[idx] : 0;
    sp[t] = v;
    __syncthreads();
    #pragma unroll
    for (int off = 1; off < 256; off <<= 1) {
        int u = (t >= off) ? sp[t - off] : 0;
        __syncthreads();
        sp[t] += u;
        __syncthreads();
    }
    if (idx < NN) g_off[idx] = sp[t] - v;
    if (t == 255) g_blk[b] = sp[255];
}
__global__ __launch_bounds__(256) void k_scan2() {
    __shared__ int sp[256];
    int t = threadIdx.x;
    int v = (t < NBLK) ? g_blk[t] : 0;
    sp[t] = v;
    __syncthreads();
    #pragma unroll
    for (int off = 1; off < 256; off <<= 1) {
        int u = (t >= off) ? sp[t - off] : 0;
        __syncthreads();
        sp[t] += u;
        __syncthreads();
    }
    if (t < NBLK) g_blkoff[t] = sp[t] - v;
}
__global__ __launch_bounds__(256) void k_scan3() {
    int idx = blockIdx.x * blockDim.x + threadIdx.x;
    if (idx < NN) {
        int o = g_off[idx] + g_blkoff[idx >> 8];
        g_off[idx] = o;
        g_cur[idx] = o;
    }
    if (idx == 0) g_off[NN] = NE;
}

// ---------------- K4: scatter ----------------
__global__ __launch_bounds__(256) void k_scatter(const int* __restrict__ ei) {
    int e = blockIdx.x * blockDim.x + threadIdx.x;
    if (e >= NE) return;
    int src = ei[e];
    int dst = ei[NE + e];
    int p = atomicAdd(&g_cur[dst], 1);
    g_sorted[p] = src;
}

// ---------------- K5: per-node softmax + weighted aggregation (warp per node) ------
__global__ __launch_bounds__(256) void k_node(const float* __restrict__ bias,
                                              float* __restrict__ out) {
    int n = (blockIdx.x * blockDim.x + threadIdx.x) >> 5;
    if (n >= NN) return;
    int lane = threadIdx.x & 31;

    int s0 = g_off[n];
    int s1 = g_off[n + 1];

    float ad = g_adst[n * HEADS + (lane & 7)];

    float den = 0.0f;
    for (int e = s0; e < s1; e++) {
        int s = g_sorted[e];
        float v = g_asrc[s * HEADS + (lane & 7)] + ad;
        v = (v > 0.0f) ? v : NEG_SLOPE * v;
        den += __expf(v);
    }
    float rden = (den > 0.0f) ? (1.0f / den) : 0.0f;

    float acc[8];
    #pragma unroll
    for (int j = 0; j < 8; j++) acc[j] = 0.0f;

    for (int e = s0; e < s1; e++) {
        int s = g_sorted[e];
        float v = g_asrc[s * HEADS + (lane & 7)] + ad;
        v = (v > 0.0f) ? v : NEG_SLOPE * v;
        float al = __expf(v) * rden;
        float a = __shfl_sync(0xffffffffu, al, lane >> 2);   // head for my 8 cols
        uint4 hv = *(const uint4*)(g_hh + (size_t)s * FOUT + lane * 8);
        const __half2* hp = (const __half2*)&hv;
        #pragma unroll
        for (int j = 0; j < 4; j++) {
            float2 f = __half22float2(hp[j]);
            acc[2 * j]     += a * f.x;
            acc[2 * j + 1] += a * f.y;
        }
    }

    const float* bp = bias + lane * 8;
    float* op = out + (size_t)n * FOUT + lane * 8;
    float4 o0 = make_float4(acc[0] + bp[0], acc[1] + bp[1], acc[2] + bp[2], acc[3] + bp[3]);
    float4 o1 = make_float4(acc[4] + bp[4], acc[5] + bp[5], acc[6] + bp[6], acc[7] + bp[7]);
    *(float4*)(op)     = o0;
    *(float4*)(op + 4) = o1;
}

// ---------------- launch ----------------
extern "C" void kernel_launch(void* const* d_in, const int* in_sizes, int n_in,
                              void* d_out, int out_size) {
    const float* x       = (const float*)d_in[0];
    const float* W       = (const float*)d_in[1];
    const float* att_src = (const float*)d_in[2];
    const float* att_dst = (const float*)d_in[3];
    const float* bias    = (const float*)d_in[4];
    const int*   ei      = (const int*)d_in[5];
    float*       out     = (float*)d_out;

    int eb = (NE + 255) / 256;

    k_zero<<<(NN + 255) / 256, 256>>>();          // 1
    k_hist<<<eb, 256>>>(ei);                      // 2
    k_scan1<<<NBLK, 256>>>();                     // 3

    dim3 ggrid(FOUT / 128, (NN + 127) / 128);     // (2, 391)
    k_gemm<<<ggrid, 256>>>(x, W, att_src, att_dst);  // 4  <- profiled slot

    k_scan2<<<1, 256>>>();                        // 5
    k_scan3<<<NBLK, 256>>>();                     // 6
    k_scatter<<<eb, 256>>>(ei);                   // 7
    k_node<<<(NN * 32 + 255) / 256, 256>>>(bias, out);  // 8
}

// round 10
// speedup vs baseline: 1.3046x; 1.1477x over previous
#include <cuda_runtime.h>
#include <cuda_fp16.h>
#include <cstdint>

// GATSingleLayer: N=50000, E=1e6, F_IN=256, HEADS=8, F_HEAD=32
#define NN      50000
#define NE      1000000
#define FIN     256
#define HEADS   8
#define FHEAD   32
#define FOUT    256
#define NEG_SLOPE 0.2f
#define NBLK    196              // ceil(NN/256)
#define KC      32               // K chunk
#define NCH     (FIN / KC)       // 8 chunks
#define PITCH   136              // smem row pitch (floats): conflict-free frag loads

// ---------------- device scratch ----------------
__device__ __align__(16) __half g_hh[(size_t)NN * FOUT]; // 25.6 MB fp16 messages
__device__ __align__(16) float g_asrc[NN * HEADS];
__device__ __align__(16) float g_adst[NN * HEADS];
__device__ int g_cnt[NN];
__device__ int g_off[NN + 1];
__device__ int g_cur[NN];
__device__ int g_sorted[NE];
__device__ int g_blk[NBLK];
__device__ int g_blkoff[NBLK];

// ---------------- helpers ----------------
__device__ __forceinline__ uint32_t tf32r(float x) {
    uint32_t u;
    asm("cvt.rna.tf32.f32 %0, %1;" : "=r"(u) : "f"(x));
    return u;
}
__device__ __forceinline__ void mma8(float* d, const uint32_t* a, uint32_t b0, uint32_t b1) {
    asm volatile("mma.sync.aligned.m16n8k8.row.col.f32.tf32.tf32.f32 "
                 "{%0,%1,%2,%3}, {%4,%5,%6,%7}, {%8,%9}, {%0,%1,%2,%3};"
                 : "+f"(d[0]), "+f"(d[1]), "+f"(d[2]), "+f"(d[3])
                 : "r"(a[0]), "r"(a[1]), "r"(a[2]), "r"(a[3]), "r"(b0), "r"(b1));
}

// ---------------- K0: zero histogram ----------------
__global__ void k_zero() {
    int i = blockIdx.x * blockDim.x + threadIdx.x;
    if (i < NN) g_cnt[i] = 0;
}

// ---------------- K1: tf32 mma.sync GEMM h = x@W (3-product split), fused epilogue --
__global__ __launch_bounds__(256) void k_gemm(const float* __restrict__ X,
                                              const float* __restrict__ W,
                                              const float* __restrict__ att_src,
                                              const float* __restrict__ att_dst) {
    __shared__ __align__(16) float As[KC][PITCH];   // [k][m]
    __shared__ __align__(16) float Bs[KC][PITCH];   // [k][n]
    __shared__ float s_as[128], s_ad[128];

    const int tid  = threadIdx.x;
    const int wid  = tid >> 5;
    const int lane = tid & 31;
    const int f0   = blockIdx.x * 128;
    const int m0   = blockIdx.y * 128;

    if (tid < 128) {
        s_as[tid] = att_src[f0 + tid];
        s_ad[tid] = att_dst[f0 + tid];
    }

    const int warp_m = wid & 3;           // 0..3 -> 32-row slice
    const int warp_n = wid >> 2;          // 0..1 -> 64-col slice
    const int mb = warp_m * 32;
    const int nb = warp_n * 64;
    const int lr = lane >> 2;             // 0..7
    const int lc = lane & 3;              // 0..3

    // A loader: row = tid&127, k-quads (tid>>7)*4 + j (j=0..3)
    const int rowA = tid & 127;
    const int kqA0 = (tid >> 7) * 4;
    const bool aval = (m0 + rowA) < NN;
    const float* Aptr = X + (size_t)(m0 + rowA) * FIN + kqA0 * 4;

    // B loader: per j: idx = tid + 256j -> k = idx>>5, nq = idx&31
    const int kB0 = tid >> 5;             // +8j
    const int nqB = tid & 31;
    const float* Bptr = W + (size_t)kB0 * FOUT + f0 + nqB * 4;

    float acc[2][8][4];
    #pragma unroll
    for (int i = 0; i < 2; i++)
        #pragma unroll
        for (int j = 0; j < 8; j++)
            #pragma unroll
            for (int q = 0; q < 4; q++) acc[i][j][q] = 0.0f;

    float4 pa[4], pb[4];
    #pragma unroll
    for (int j = 0; j < 4; j++) {
        pa[j] = aval ? *(const float4*)(Aptr + j * 4) : make_float4(0.f, 0.f, 0.f, 0.f);
        pb[j] = *(const float4*)(Bptr + (size_t)(8 * j) * FOUT);
    }

    for (int kt = 0; kt < NCH; kt++) {
        // commit prefetched chunk to smem
        #pragma unroll
        for (int j = 0; j < 4; j++) {
            int kq = kqA0 + j;
            As[kq * 4 + 0][rowA] = pa[j].x;
            As[kq * 4 + 1][rowA] = pa[j].y;
            As[kq * 4 + 2][rowA] = pa[j].z;
            As[kq * 4 + 3][rowA] = pa[j].w;
            *(float4*)&Bs[kB0 + 8 * j][nqB * 4] = pb[j];
        }
        __syncthreads();

        // prefetch next chunk
        if (kt + 1 < NCH) {
            const float* ap = Aptr + (kt + 1) * KC;
            const float* bp = Bptr + (size_t)(kt + 1) * KC * FOUT;
            #pragma unroll
            for (int j = 0; j < 4; j++) {
                pa[j] = aval ? *(const float4*)(ap + j * 4) : make_float4(0.f, 0.f, 0.f, 0.f);
                pb[j] = *(const float4*)(bp + (size_t)(8 * j) * FOUT);
            }
        }

        #pragma unroll
        for (int k8 = 0; k8 < KC / 8; k8++) {
            const int kb = k8 * 8;
            // A fragments (2 m-tiles), split hi/lo
            uint32_t ahi[2][4], alo[2][4];
            #pragma unroll
            for (int wm = 0; wm < 2; wm++) {
                int r = mb + wm * 16 + lr;
                float a0 = As[kb + lc][r];
                float a1 = As[kb + lc][r + 8];
                float a2 = As[kb + lc + 4][r];
                float a3 = As[kb + lc + 4][r + 8];
                ahi[wm][0] = tf32r(a0); alo[wm][0] = __float_as_uint(a0 - __uint_as_float(ahi[wm][0]));
                ahi[wm][1] = tf32r(a1); alo[wm][1] = __float_as_uint(a1 - __uint_as_float(ahi[wm][1]));
                ahi[wm][2] = tf32r(a2); alo[wm][2] = __float_as_uint(a2 - __uint_as_float(ahi[wm][2]));
                ahi[wm][3] = tf32r(a3); alo[wm][3] = __float_as_uint(a3 - __uint_as_float(ahi[wm][3]));
            }
            #pragma unroll
            for (int wn = 0; wn < 8; wn++) {
                int bc = nb + wn * 8 + lr;
                float b0 = Bs[kb + lc][bc];
                float b1 = Bs[kb + lc + 4][bc];
                uint32_t bh0 = tf32r(b0), bh1 = tf32r(b1);
                uint32_t bl0 = __float_as_uint(b0 - __uint_as_float(bh0));
                uint32_t bl1 = __float_as_uint(b1 - __uint_as_float(bh1));
                #pragma unroll
                for (int wm = 0; wm < 2; wm++) {
                    mma8(acc[wm][wn], ahi[wm], bh0, bh1);
                    mma8(acc[wm][wn], alo[wm], bh0, bh1);
                    mma8(acc[wm][wn], ahi[wm], bl0, bl1);
                }
            }
        }
        __syncthreads();
    }

    // ---- epilogue: h store (fp16) + fused a_src/a_dst ----
    // acc[wm][wn]: d0=(lr, 2lc), d1=(lr, 2lc+1), d2=(lr+8, 2lc), d3=(lr+8, 2lc+1)
    #pragma unroll
    for (int wm = 0; wm < 2; wm++) {
        #pragma unroll
        for (int half = 0; half < 2; half++) {
            int m = m0 + mb + wm * 16 + half * 8 + lr;
            bool mval = m < NN;
            // h store: one half2 per wn tile
            if (mval) {
                __half* hp = g_hh + (size_t)m * FOUT + f0 + nb + lc * 2;
                #pragma unroll
                for (int wn = 0; wn < 8; wn++) {
                    __half2 hv = __floats2half2_rn(acc[wm][wn][2 * half],
                                                   acc[wm][wn][2 * half + 1]);
                    *(__half2*)(hp + wn * 8) = hv;
                }
            }
            // att dots: head A = wn 0..3, head B = wn 4..7 (within this warp's 64 cols)
            float psA = 0.f, pdA = 0.f, psB = 0.f, pdB = 0.f;
            #pragma unroll
            for (int wn = 0; wn < 8; wn++) {
                int col = nb + wn * 8 + lc * 2;
                float v0 = acc[wm][wn][2 * half];
                float v1 = acc[wm][wn][2 * half + 1];
                float s = v0 * s_as[col] + v1 * s_as[col + 1];
                float d = v0 * s_ad[col] + v1 * s_ad[col + 1];
                if (wn < 4) { psA += s; pdA += d; }
                else        { psB += s; pdB += d; }
            }
            // reduce over the 4 lanes (lc 0..3) sharing this row
            #pragma unroll
            for (int off = 1; off < 4; off <<= 1) {
                psA += __shfl_xor_sync(0xffffffffu, psA, off);
                pdA += __shfl_xor_sync(0xffffffffu, pdA, off);
                psB += __shfl_xor_sync(0xffffffffu, psB, off);
                pdB += __shfl_xor_sync(0xffffffffu, pdB, off);
            }
            if (lc == 0 && mval) {
                int headA = ((f0 + nb) >> 5);
                g_asrc[m * HEADS + headA]     = psA;
                g_adst[m * HEADS + headA]     = pdA;
                g_asrc[m * HEADS + headA + 1] = psB;
                g_adst[m * HEADS + headA + 1] = pdB;
            }
        }
    }
}

// ---------------- K2: degree histogram ----------------
__global__ __launch_bounds__(256) void k_hist(const int* __restrict__ ei) {
    int e = blockIdx.x * blockDim.x + threadIdx.x;
    if (e < NE) atomicAdd(&g_cnt[ei[NE + e]], 1);
}

// ---------------- K3a/b/c: multi-block scan ----------------
__global__ __launch_bounds__(256) void k_scan1() {
    __shared__ int sp[256];
    int b = blockIdx.x, t = threadIdx.x;
    int idx = b * 256 + t;
    int v = (idx < NN) ? g_cnt[idx] : 0;
    sp[t] = v;
    __syncthreads();
    #pragma unroll
    for (int off = 1; off < 256; off <<= 1) {
        int u = (t >= off) ? sp[t - off] : 0;
        __syncthreads();
        sp[t] += u;
        __syncthreads();
    }
    if (idx < NN) g_off[idx] = sp[t] - v;
    if (t == 255) g_blk[b] = sp[255];
}
__global__ __launch_bounds__(256) void k_scan2() {
    __shared__ int sp[256];
    int t = threadIdx.x;
    int v = (t < NBLK) ? g_blk[t] : 0;
    sp[t] = v;
    __syncthreads();
    #pragma unroll
    for (int off = 1; off < 256; off <<= 1) {
        int u = (t >= off) ? sp[t - off] : 0;
        __syncthreads();
        sp[t] += u;
        __syncthreads();
    }
    if (t < NBLK) g_blkoff[t] = sp[t] - v;
}
__global__ __launch_bounds__(256) void k_scan3() {
    int idx = blockIdx.x * blockDim.x + threadIdx.x;
    if (idx < NN) {
        int o = g_off[idx] + g_blkoff[idx >> 8];
        g_off[idx] = o;
        g_cur[idx] = o;
    }
    if (idx == 0) g_off[NN] = NE;
}

// ---------------- K4: scatter ----------------
__global__ __launch_bounds__(256) void k_scatter(const int* __restrict__ ei) {
    int e = blockIdx.x * blockDim.x + threadIdx.x;
    if (e >= NE) return;
    int src = ei[e];
    int dst = ei[NE + e];
    int p = atomicAdd(&g_cur[dst], 1);
    g_sorted[p] = src;
}

// ---------------- K5: per-node softmax + weighted aggregation (warp per node) ------
__global__ __launch_bounds__(256) void k_node(const float* __restrict__ bias,
                                              float* __restrict__ out) {
    int n = (blockIdx.x * blockDim.x + threadIdx.x) >> 5;
    if (n >= NN) return;
    int lane = threadIdx.x & 31;

    int s0 = g_off[n];
    int s1 = g_off[n + 1];

    float ad = g_adst[n * HEADS + (lane & 7)];

    float den = 0.0f;
    for (int e = s0; e < s1; e++) {
        int s = g_sorted[e];
        float v = g_asrc[s * HEADS + (lane & 7)] + ad;
        v = (v > 0.0f) ? v : NEG_SLOPE * v;
        den += __expf(v);
    }
    float rden = (den > 0.0f) ? (1.0f / den) : 0.0f;

    float acc[8];
    #pragma unroll
    for (int j = 0; j < 8; j++) acc[j] = 0.0f;

    for (int e = s0; e < s1; e++) {
        int s = g_sorted[e];
        float v = g_asrc[s * HEADS + (lane & 7)] + ad;
        v = (v > 0.0f) ? v : NEG_SLOPE * v;
        float al = __expf(v) * rden;
        float a = __shfl_sync(0xffffffffu, al, lane >> 2);   // head for my 8 cols
        uint4 hv = *(const uint4*)(g_hh + (size_t)s * FOUT + lane * 8);
        const __half2* hp = (const __half2*)&hv;
        #pragma unroll
        for (int j = 0; j < 4; j++) {
            float2 f = __half22float2(hp[j]);
            acc[2 * j]     += a * f.x;
            acc[2 * j + 1] += a * f.y;
        }
    }

    const float* bp = bias + lane * 8;
    float* op = out + (size_t)n * FOUT + lane * 8;
    float4 o0 = make_float4(acc[0] + bp[0], acc[1] + bp[1], acc[2] + bp[2], acc[3] + bp[3]);
    float4 o1 = make_float4(acc[4] + bp[4], acc[5] + bp[5], acc[6] + bp[6], acc[7] + bp[7]);
    *(float4*)(op)     = o0;
    *(float4*)(op + 4) = o1;
}

// ---------------- launch ----------------
extern "C" void kernel_launch(void* const* d_in, const int* in_sizes, int n_in,
                              void* d_out, int out_size) {
    const float* x       = (const float*)d_in[0];
    const float* W       = (const float*)d_in[1];
    const float* att_src = (const float*)d_in[2];
    const float* att_dst = (const float*)d_in[3];
    const float* bias    = (const float*)d_in[4];
    const int*   ei      = (const int*)d_in[5];
    float*       out     = (float*)d_out;

    int eb = (NE + 255) / 256;

    k_zero<<<(NN + 255) / 256, 256>>>();          // 1
    k_hist<<<eb, 256>>>(ei);                      // 2
    k_scan1<<<NBLK, 256>>>();                     // 3

    dim3 ggrid(FOUT / 128, (NN + 127) / 128);     // (2, 391)
    k_gemm<<<ggrid, 256>>>(x, W, att_src, att_dst);  // 4  <- profiled slot

    k_scan2<<<1, 256>>>();                        // 5
    k_scan3<<<NBLK, 256>>>();                     // 6
    k_scatter<<<eb, 256>>>(ei);                   // 7
    k_node<<<(NN * 32 + 255) / 256, 256>>>(bias, out);  // 8
}